// round 9
// baseline (speedup 1.0000x reference)
#include <cuda_runtime.h>
#include <cuda_bf16.h>
#include <cstdint>

// Problem constants
#define T_SEQ 65536
#define F_IN  512
#define H_DIM 64
#define G_DIM 256    // 4*H
#define NT4   (T_SEQ / 4)
#define NSTRIP (T_SEQ / 64)   // 1024 flag strips, 64 timesteps each

typedef unsigned long long ull;

// Scratch (allocation-free rule: __device__ globals)
__device__ __align__(16) float4 g_xgA[(size_t)(NT4 + 2) * 128];
__device__ __align__(16) float4 g_xgB[(size_t)(NT4 + 2) * 128];
__device__ float g_hfin[H_DIM];
__device__ int g_flag[NSTRIP];          // per-strip producer counters (0..4)

// ---------------- packed f32x2 helpers ----------------
static __device__ __forceinline__ ull fma2(ull a, ull b, ull c) {
    ull d;
    asm("fma.rn.f32x2 %0, %1, %2, %3;" : "=l"(d) : "l"(a), "l"(b), "l"(c));
    return d;
}
static __device__ __forceinline__ ull add2(ull a, ull b) {
    ull d;
    asm("add.rn.f32x2 %0, %1, %2;" : "=l"(d) : "l"(a), "l"(b));
    return d;
}
static __device__ __forceinline__ float2 upk(ull a) {
    float2 r;
    asm("mov.b64 {%0, %1}, %2;" : "=f"(r.x), "=f"(r.y) : "l"(a));
    return r;
}
static __device__ __forceinline__ ull pk2(float x, float y) {
    ull r;
    asm("mov.b64 %0, {%1, %2};" : "=l"(r) : "f"(x), "f"(y));
    return r;
}

// ---------------- single-instruction MUFU.TANH ----------------
static __device__ __forceinline__ float tanhap(float x) {
    float r;
    asm("tanh.approx.f32 %0, %1;" : "=f"(r) : "f"(x));
    return r;
}

// 4-warp named barrier (id 1, 128 threads) for the consumer
static __device__ __forceinline__ void nbar128() {
    asm volatile("bar.sync 1, 128;" ::: "memory");
}

// Recurrence thread mapping for gate-row r (= g*64 + u)
static __device__ __forceinline__ int map_tid(int g, int u) {
    int odd = g & 1;                 // i,g -> even ; f,o -> odd
    return ((u >> 4) << 5) + ((u & 15) << 1) + odd;
}

// =====================================================================
// Kernel 0: reset strip flags (each replay, before the fused kernel)
// =====================================================================
__global__ void zero_flags() {
    int i = blockIdx.x * blockDim.x + threadIdx.x;
    if (i < NSTRIP) g_flag[i] = 0;
}

// =====================================================================
// Fused kernel: block 0 = LSTM recurrence consumer (warps 0-3 only;
// warps 4-7 exit at entry so the per-step barrier is 4-warp named bar),
// blocks 1..4096 = GEMM tile producers with per-strip release flags.
// Producer p = bid-1: t-strip = p>>2, colgroup = p&3 (strips finish in
// t-order under bid-ordered scheduling).
// =====================================================================
__global__ void __launch_bounds__(256, 1)
lstm_fused(const float* __restrict__ x,
           const float* __restrict__ Wih,
           const float* __restrict__ bih,
           const float* __restrict__ bhh,
           const float* __restrict__ Whh,
           const float* __restrict__ h0,
           const float* __restrict__ c0) {
    __shared__ float xs[64][17];
    __shared__ float ws[64][17];
    __shared__ __align__(16) float h_sh[2][H_DIM];

    const int tid = threadIdx.x;

    if (blockIdx.x != 0) {
        // ================== PRODUCER: one 64x64 xg tile ==================
        const int p = blockIdx.x - 1;
        const int trow = p >> 2;           // t-strip index
        const int row0 = trow * 64;
        const int col0 = (p & 3) * 64;
        const int tx = tid & 15, ty = tid >> 4;

        float acc[4][4];
#pragma unroll
        for (int i = 0; i < 4; i++)
#pragma unroll
            for (int j = 0; j < 4; j++) acc[i][j] = 0.0f;

        const int l = tid * 4;
        const int lr = l >> 4, lk = l & 15;

        for (int kb = 0; kb < F_IN; kb += 16) {
            float4 xv = *(const float4*)(x + (size_t)(row0 + lr) * F_IN + kb + lk);
            float4 wv = *(const float4*)(Wih + (size_t)(col0 + lr) * F_IN + kb + lk);
            xs[lr][lk] = xv.x; xs[lr][lk + 1] = xv.y; xs[lr][lk + 2] = xv.z; xs[lr][lk + 3] = xv.w;
            ws[lr][lk] = wv.x; ws[lr][lk + 1] = wv.y; ws[lr][lk + 2] = wv.z; ws[lr][lk + 3] = wv.w;
            __syncthreads();
#pragma unroll
            for (int kk = 0; kk < 16; kk++) {
                float a[4], b[4];
#pragma unroll
                for (int i = 0; i < 4; i++) a[i] = xs[ty * 4 + i][kk];
#pragma unroll
                for (int j = 0; j < 4; j++) b[j] = ws[tx * 4 + j][kk];
#pragma unroll
                for (int i = 0; i < 4; i++)
#pragma unroll
                    for (int j = 0; j < 4; j++) acc[i][j] = fmaf(a[i], b[j], acc[i][j]);
            }
            __syncthreads();
        }

        const int tb4 = (row0 + ty * 4) >> 2;
#pragma unroll
        for (int j = 0; j < 4; j++) {
            const int col = col0 + tx * 4 + j;
            const float bj = bih[col] + bhh[col];
            const int gg = col >> 6;            // gate 0=i 1=f 2=g 3=o
            const int uu = col & 63;
            const int pp = map_tid(gg, uu);
            const float sc = (gg == 2) ? 1.0f : 0.5f;  // sigmoid pre-scale (exact)
            float4 o;
            o.x = sc * (acc[0][j] + bj);
            o.y = sc * (acc[1][j] + bj);
            o.z = sc * (acc[2][j] + bj);
            o.w = sc * (acc[3][j] + bj);
            float4* buf = (gg >= 2) ? g_xgB : g_xgA;   // slot B = gates g,o
            buf[(size_t)tb4 * 128 + pp] = o;
        }

        // Publish: fence all stores, then one thread releases the strip count.
        __threadfence();
        __syncthreads();
        if (tid == 0) atomicAdd(&g_flag[trow], 1);
        return;
    }

    // ================== CONSUMER: LSTM recurrence ==================
    if (tid >= 128) return;   // warps 4-7 leave; barrier below is 4-warp named

    const int l = tid & 31;
    const int u = ((tid >> 5) << 4) + (l >> 1);   // hidden unit
    const int odd = l & 1;
    const int rA = (odd ? 64 : 0) + u;    // i or f   (sigmoid: pre-scale 0.5)
    const int rB = (odd ? 192 : 128) + u; // g or o   (tanh 1.0 / sigmoid 0.5)
    const float scA = 0.5f;
    const float scB = odd ? 0.5f : 1.0f;

    // W_hh rows -> packed f32x2 registers, pre-scaled (x0.5 exact)
    ull wA[32], wB[32];
    {
        const float2* pa = (const float2*)(Whh + (size_t)rA * H_DIM);
        const float2* pb = (const float2*)(Whh + (size_t)rB * H_DIM);
#pragma unroll
        for (int i = 0; i < 32; i++) {
            float2 va = pa[i], vb = pb[i];
            wA[i] = pk2(scA * va.x, scA * va.y);
            wB[i] = pk2(scB * vb.x, scB * vb.y);
        }
    }

    const float aB = odd ? 0.5f : 1.0f;
    const float oB = odd ? 0.5f : 0.0f;

    float c = odd ? c0[u] : 0.0f;
    float h = 0.0f;
    if (tid < H_DIM) h_sh[0][tid] = h0[tid];

    volatile int* vflag = (volatile int*)g_flag;

#define WAIT_STRIP(S) do {                                                    \
        int _s = (S);                                                         \
        if (_s < NSTRIP) {                                                    \
            while (vflag[_s] < 4) { }                                         \
            __threadfence();                                                  \
        }                                                                     \
    } while (0)

#define STEP(XA, XB, RB, WB) do {                                             \
        nbar128();                                                            \
        const ulonglong2* hp = (const ulonglong2*)h_sh[RB];                   \
        ull a0 = 0, a1 = 0, a2 = 0, a3 = 0;                                   \
        ull b0 = 0, b1 = 0, b2 = 0, b3 = 0;                                   \
        _Pragma("unroll")                                                     \
        for (int i = 0; i < 8; i++) {                                         \
            ulonglong2 hv = hp[2 * i], hw = hp[2 * i + 1];                    \
            a0 = fma2(hv.x, wA[4 * i + 0], a0);                               \
            b0 = fma2(hv.x, wB[4 * i + 0], b0);                               \
            a1 = fma2(hv.y, wA[4 * i + 1], a1);                               \
            b1 = fma2(hv.y, wB[4 * i + 1], b1);                               \
            a2 = fma2(hw.x, wA[4 * i + 2], a2);                               \
            b2 = fma2(hw.x, wB[4 * i + 2], b2);                               \
            a3 = fma2(hw.y, wA[4 * i + 3], a3);                               \
            b3 = fma2(hw.y, wB[4 * i + 3], b3);                               \
        }                                                                     \
        float2 sA = upk(add2(add2(a0, a1), add2(a2, a3)));                    \
        float2 sB = upk(add2(add2(b0, b1), add2(b2, b3)));                    \
        float preA = (XA) + sA.x + sA.y;                                      \
        float preB = (XB) + sB.x + sB.y;                                      \
        float vA = fmaf(0.5f, tanhap(preA), 0.5f);   /* sigmoid */            \
        float vB = fmaf(aB, tanhap(preB), oB);       /* tanh / sigmoid */     \
        float pr = __shfl_sync(0xffffffffu, vA * vB, l & 30);  /* i*g~ */     \
        if (odd) {                                                            \
            c = fmaf(vA, c, pr);            /* c = f*c + i*g~ */              \
            h = vB * tanhap(c);             /* h = o*tanh(c) */               \
            h_sh[WB][u] = h;                                                  \
        }                                                                     \
    } while (0)

    // Wait for strip 0, make h_sh[0] + strip-0 data visible, prime stream.
    WAIT_STRIP(0);
    nbar128();

    float4 xA0 = g_xgA[tid],       xB0 = g_xgB[tid];
    float4 xA1 = g_xgA[128 + tid], xB1 = g_xgB[128 + tid];

    for (int tb = 0; tb < NT4; tb++) {
        // Prefetch target crosses into a new strip? Wait before touching it.
        if (((tb + 2) & 15) == 0) WAIT_STRIP((tb + 2) >> 4);
        float4 xA2 = g_xgA[(size_t)(tb + 2) * 128 + tid];
        float4 xB2 = g_xgB[(size_t)(tb + 2) * 128 + tid];
        STEP(xA0.x, xB0.x, 0, 1);
        STEP(xA0.y, xB0.y, 1, 0);
        STEP(xA0.z, xB0.z, 0, 1);
        STEP(xA0.w, xB0.w, 1, 0);
        xA0 = xA1; xA1 = xA2;
        xB0 = xB1; xB1 = xB2;
    }
#undef STEP
#undef WAIT_STRIP

    if (odd) g_hfin[u] = h;
}

// =====================================================================
// Kernel 3: out[f] = sigmoid(h_last . W_fc[f] + b_fc[f]),  f < 512
// =====================================================================
__global__ void fc_out(const float* __restrict__ Wfc,
                       const float* __restrict__ bfc,
                       float* __restrict__ out) {
    __shared__ float hsm[H_DIM];
    const int tid = threadIdx.x;   // 0..511
    if (tid < H_DIM) hsm[tid] = g_hfin[tid];
    __syncthreads();
    float acc = bfc[tid];
    const float* wr = Wfc + (size_t)tid * H_DIM;
#pragma unroll
    for (int k = 0; k < H_DIM; k++) acc = fmaf(wr[k], hsm[k], acc);
    out[tid] = 1.0f / (1.0f + __expf(-acc));
}

extern "C" void kernel_launch(void* const* d_in, const int* in_sizes, int n_in,
                              void* d_out, int out_size) {
    const float* x   = (const float*)d_in[0];
    const float* h0  = (const float*)d_in[1];
    const float* c0  = (const float*)d_in[2];
    const float* Wih = (const float*)d_in[3];
    const float* Whh = (const float*)d_in[4];
    const float* bih = (const float*)d_in[5];
    const float* bhh = (const float*)d_in[6];
    const float* Wfc = (const float*)d_in[7];
    const float* bfc = (const float*)d_in[8];
    float* out = (float*)d_out;

    zero_flags<<<(NSTRIP + 255) / 256, 256>>>();
    lstm_fused<<<1 + (T_SEQ / 64) * 4, 256>>>(x, Wih, bih, bhh, Whh, h0, c0);
    fc_out<<<1, 512>>>(Wfc, bfc, out);
}

// round 10
// speedup vs baseline: 1.5370x; 1.5370x over previous
#include <cuda_runtime.h>
#include <cuda_bf16.h>
#include <cstdint>

// Problem constants
#define T_SEQ 65536
#define F_IN  512
#define H_DIM 64
#define G_DIM 256    // 4*H
#define NT4   (T_SEQ / 4)

typedef unsigned long long ull;

// Scratch (allocation-free rule: __device__ globals)
// Slot streams as float4 (4 timesteps per load), padded +2 blocks.
__device__ __align__(16) float4 g_xgA[(size_t)(NT4 + 2) * 128];
__device__ __align__(16) float4 g_xgB[(size_t)(NT4 + 2) * 128];
__device__ float g_hfin[H_DIM];

// ---------------- packed f32x2 helpers ----------------
static __device__ __forceinline__ ull fma2(ull a, ull b, ull c) {
    ull d;
    asm("fma.rn.f32x2 %0, %1, %2, %3;" : "=l"(d) : "l"(a), "l"(b), "l"(c));
    return d;
}
static __device__ __forceinline__ ull add2(ull a, ull b) {
    ull d;
    asm("add.rn.f32x2 %0, %1, %2;" : "=l"(d) : "l"(a), "l"(b));
    return d;
}
static __device__ __forceinline__ float2 upk(ull a) {
    float2 r;
    asm("mov.b64 {%0, %1}, %2;" : "=f"(r.x), "=f"(r.y) : "l"(a));
    return r;
}
static __device__ __forceinline__ ull pk2(float x, float y) {
    ull r;
    asm("mov.b64 %0, {%1, %2};" : "=l"(r) : "f"(x), "f"(y));
    return r;
}

// ---------------- single-instruction MUFU.TANH ----------------
static __device__ __forceinline__ float tanhap(float x) {
    float r;
    asm("tanh.approx.f32 %0, %1;" : "=f"(r) : "f"(x));
    return r;
}

// Recurrence thread mapping for gate-row r (= g*64 + u):
// warp w = u>>4 owns units [16w,16w+16); even lane: gates (i,g); odd: (f,o)
static __device__ __forceinline__ int map_tid(int g, int u) {
    int odd = g & 1;                 // i,g -> even ; f,o -> odd
    return ((u >> 4) << 5) + ((u & 15) << 1) + odd;
}

// =====================================================================
// Kernel 1: xg = x @ W_ih.T + (b_ih + b_hh), permuted into slot streams.
// BM=64 (timesteps), BN=256 (ALL gate rows) -> x is read exactly once.
// Thread layout 64x4: tx=tid&63 covers 4 cols each, ty=tid>>6 covers 16
// rows each. Same k accumulation order as before (bit-identical xg).
// =====================================================================
__global__ void __launch_bounds__(256)
gemm_xg(const float* __restrict__ x,
        const float* __restrict__ Wih,
        const float* __restrict__ bih,
        const float* __restrict__ bhh) {
    __shared__ float xs[64][17];
    __shared__ float ws[G_DIM][17];
    const int tid = threadIdx.x;           // 0..255
    const int tx = tid & 63;               // col group (4 cols)
    const int ty = tid >> 6;               // row group (16 rows)
    const int row0 = blockIdx.x * 64;      // t-tile base

    float acc[16][4];
#pragma unroll
    for (int i = 0; i < 16; i++)
#pragma unroll
        for (int j = 0; j < 4; j++) acc[i][j] = 0.0f;

    const int l = tid * 4;
    const int lr = l >> 4, lk = l & 15;    // x-tile loader (4 floats/thread)

    for (int kb = 0; kb < F_IN; kb += 16) {
        // x tile: 64 x 16
        float4 xv = *(const float4*)(x + (size_t)(row0 + lr) * F_IN + kb + lk);
        xs[lr][lk] = xv.x; xs[lr][lk + 1] = xv.y; xs[lr][lk + 2] = xv.z; xs[lr][lk + 3] = xv.w;
        // W tile: 256 x 16 — thread tid loads its whole row slice
        {
            const float* wr = Wih + (size_t)tid * F_IN + kb;
            float4 w0 = *(const float4*)(wr + 0);
            float4 w1 = *(const float4*)(wr + 4);
            float4 w2 = *(const float4*)(wr + 8);
            float4 w3 = *(const float4*)(wr + 12);
            ws[tid][0]  = w0.x; ws[tid][1]  = w0.y; ws[tid][2]  = w0.z; ws[tid][3]  = w0.w;
            ws[tid][4]  = w1.x; ws[tid][5]  = w1.y; ws[tid][6]  = w1.z; ws[tid][7]  = w1.w;
            ws[tid][8]  = w2.x; ws[tid][9]  = w2.y; ws[tid][10] = w2.z; ws[tid][11] = w2.w;
            ws[tid][12] = w3.x; ws[tid][13] = w3.y; ws[tid][14] = w3.z; ws[tid][15] = w3.w;
        }
        __syncthreads();
#pragma unroll
        for (int kk = 0; kk < 16; kk++) {
            float a[16], b[4];
#pragma unroll
            for (int i = 0; i < 16; i++) a[i] = xs[ty * 16 + i][kk];
#pragma unroll
            for (int j = 0; j < 4; j++) b[j] = ws[tx * 4 + j][kk];
#pragma unroll
            for (int i = 0; i < 16; i++)
#pragma unroll
                for (int j = 0; j < 4; j++) acc[i][j] = fmaf(a[i], b[j], acc[i][j]);
        }
        __syncthreads();
    }

    // Epilogue: thread's 16 rows = 4 float4 t-blocks; 4 cols.
    const int tbb = (row0 + ty * 16) >> 2;     // first t-block
#pragma unroll
    for (int j = 0; j < 4; j++) {
        const int col = tx * 4 + j;
        const float bj = bih[col] + bhh[col];
        const int gg = col >> 6;            // gate 0=i 1=f 2=g 3=o
        const int uu = col & 63;
        const int p = map_tid(gg, uu);
        const float sc = (gg == 2) ? 1.0f : 0.5f;   // sigmoid pre-scale (exact)
        float4* buf = (gg >= 2) ? g_xgB : g_xgA;    // slot B = gates g,o
#pragma unroll
        for (int m = 0; m < 4; m++) {
            float4 o;
            o.x = sc * (acc[4 * m + 0][j] + bj);
            o.y = sc * (acc[4 * m + 1][j] + bj);
            o.z = sc * (acc[4 * m + 2][j] + bj);
            o.w = sc * (acc[4 * m + 3][j] + bj);
            buf[(size_t)(tbb + m) * 128 + p] = o;
        }
    }
}

// =====================================================================
// Kernel 2: persistent single-block LSTM recurrence, 128 threads
// (4 warps, 1 per SMSP). Even lane: gates (i, g) of unit u; odd: (f, o).
// One __syncthreads per step; gate product crosses via one shfl.
// Stream loop unrolled 2x with 4-buffer static rotation (no MOVs).
// =====================================================================
__global__ void __launch_bounds__(128, 1)
lstm_rec(const float* __restrict__ Whh,
         const float* __restrict__ h0,
         const float* __restrict__ c0) {
    __shared__ __align__(16) float h_sh[2][H_DIM];
    const int tid = threadIdx.x;          // 0..127
    const int l = tid & 31;
    const int u = ((tid >> 5) << 4) + (l >> 1);   // hidden unit
    const int odd = l & 1;
    const int rA = (odd ? 64 : 0) + u;    // i or f   (sigmoid: pre-scale 0.5)
    const int rB = (odd ? 192 : 128) + u; // g or o   (tanh 1.0 / sigmoid 0.5)
    const float scA = 0.5f;
    const float scB = odd ? 0.5f : 1.0f;

    // W_hh rows -> packed f32x2 registers, pre-scaled (x0.5 exact)
    ull wA[32], wB[32];
    {
        const float2* pa = (const float2*)(Whh + (size_t)rA * H_DIM);
        const float2* pb = (const float2*)(Whh + (size_t)rB * H_DIM);
#pragma unroll
        for (int i = 0; i < 32; i++) {
            float2 va = pa[i], vb = pb[i];
            wA[i] = pk2(scA * va.x, scA * va.y);
            wB[i] = pk2(scB * vb.x, scB * vb.y);
        }
    }

    const float aB = odd ? 0.5f : 1.0f;
    const float oB = odd ? 0.5f : 0.0f;

    float c = odd ? c0[u] : 0.0f;
    float h = 0.0f;
    if (tid < H_DIM) h_sh[0][tid] = h0[tid];

#define STEP(XA, XB, RB, WB) do {                                             \
        __syncthreads();                                                      \
        const ulonglong2* hp = (const ulonglong2*)h_sh[RB];                   \
        ull a0 = 0, a1 = 0, a2 = 0, a3 = 0;                                   \
        ull b0 = 0, b1 = 0, b2 = 0, b3 = 0;                                   \
        _Pragma("unroll")                                                     \
        for (int i = 0; i < 8; i++) {                                         \
            ulonglong2 hv = hp[2 * i], hw = hp[2 * i + 1];                    \
            a0 = fma2(hv.x, wA[4 * i + 0], a0);                               \
            b0 = fma2(hv.x, wB[4 * i + 0], b0);                               \
            a1 = fma2(hv.y, wA[4 * i + 1], a1);                               \
            b1 = fma2(hv.y, wB[4 * i + 1], b1);                               \
            a2 = fma2(hw.x, wA[4 * i + 2], a2);                               \
            b2 = fma2(hw.x, wB[4 * i + 2], b2);                               \
            a3 = fma2(hw.y, wA[4 * i + 3], a3);                               \
            b3 = fma2(hw.y, wB[4 * i + 3], b3);                               \
        }                                                                     \
        float2 sA = upk(add2(add2(a0, a1), add2(a2, a3)));                    \
        float2 sB = upk(add2(add2(b0, b1), add2(b2, b3)));                    \
        float preA = (XA) + sA.x + sA.y;                                      \
        float preB = (XB) + sB.x + sB.y;                                      \
        float vA = fmaf(0.5f, tanhap(preA), 0.5f);   /* sigmoid */            \
        float vB = fmaf(aB, tanhap(preB), oB);       /* tanh / sigmoid */     \
        float pr = __shfl_sync(0xffffffffu, vA * vB, l & 30);  /* i*g~ */     \
        if (odd) {                                                            \
            c = fmaf(vA, c, pr);            /* c = f*c + i*g~ */              \
            h = vB * tanhap(c);             /* h = o*tanh(c) */               \
            h_sh[WB][u] = h;                                                  \
        }                                                                     \
    } while (0)

#define STEP4(XA4, XB4) do {                                                  \
        STEP((XA4).x, (XB4).x, 0, 1);                                         \
        STEP((XA4).y, (XB4).y, 1, 0);                                         \
        STEP((XA4).z, (XB4).z, 0, 1);                                         \
        STEP((XA4).w, (XB4).w, 1, 0);                                         \
    } while (0)

    // Streamed xg, unrolled 2x: consume (A,B) while loading (C,D), then
    // swap roles. No register MOVs, loads stay 8 steps ahead of use.
    float4 aA = g_xgA[tid],       bA = g_xgB[tid];
    float4 aB4 = g_xgA[128 + tid], bB4 = g_xgB[128 + tid];
    float4 aC, bC, aD, bD;
    for (int tb = 0; tb < NT4; tb += 4) {
        aC = g_xgA[(size_t)(tb + 2) * 128 + tid];
        bC = g_xgB[(size_t)(tb + 2) * 128 + tid];
        STEP4(aA, bA);
        aD = g_xgA[(size_t)(tb + 3) * 128 + tid];
        bD = g_xgB[(size_t)(tb + 3) * 128 + tid];
        STEP4(aB4, bB4);
        aA = g_xgA[(size_t)(tb + 4) * 128 + tid];
        bA = g_xgB[(size_t)(tb + 4) * 128 + tid];
        STEP4(aC, bC);
        aB4 = g_xgA[(size_t)(tb + 5) * 128 + tid];
        bB4 = g_xgB[(size_t)(tb + 5) * 128 + tid];
        STEP4(aD, bD);
    }
#undef STEP4
#undef STEP

    if (odd) g_hfin[u] = h;
}

// =====================================================================
// Kernel 3: out[f] = sigmoid(h_last . W_fc[f] + b_fc[f]),  f < 512
// =====================================================================
__global__ void fc_out(const float* __restrict__ Wfc,
                       const float* __restrict__ bfc,
                       float* __restrict__ out) {
    __shared__ float hsm[H_DIM];
    const int tid = threadIdx.x;   // 0..511
    if (tid < H_DIM) hsm[tid] = g_hfin[tid];
    __syncthreads();
    float acc = bfc[tid];
    const float* wr = Wfc + (size_t)tid * H_DIM;
#pragma unroll
    for (int k = 0; k < H_DIM; k++) acc = fmaf(wr[k], hsm[k], acc);
    out[tid] = 1.0f / (1.0f + __expf(-acc));
}

extern "C" void kernel_launch(void* const* d_in, const int* in_sizes, int n_in,
                              void* d_out, int out_size) {
    const float* x   = (const float*)d_in[0];
    const float* h0  = (const float*)d_in[1];
    const float* c0  = (const float*)d_in[2];
    const float* Wih = (const float*)d_in[3];
    const float* Whh = (const float*)d_in[4];
    const float* bih = (const float*)d_in[5];
    const float* bhh = (const float*)d_in[6];
    const float* Wfc = (const float*)d_in[7];
    const float* bfc = (const float*)d_in[8];
    float* out = (float*)d_out;

    gemm_xg<<<T_SEQ / 64, 256>>>(x, Wih, bih, bhh);
    lstm_rec<<<1, 128>>>(Whh, h0, c0);
    fc_out<<<1, 512>>>(Wfc, bfc, out);
}

// round 11
// speedup vs baseline: 1.6711x; 1.0873x over previous
#include <cuda_runtime.h>
#include <cuda_bf16.h>
#include <cstdint>

// Problem constants
#define T_SEQ 65536
#define F_IN  512
#define H_DIM 64
#define G_DIM 256    // 4*H
#define NT4   (T_SEQ / 4)

typedef unsigned long long ull;

// Scratch (allocation-free rule: __device__ globals)
// Slot streams as float4 (4 timesteps per load), padded +2 blocks so the
// prefetch needs no bounds predicate.
__device__ __align__(16) float4 g_xgA[(size_t)(NT4 + 2) * 128];
__device__ __align__(16) float4 g_xgB[(size_t)(NT4 + 2) * 128];
__device__ float g_hfin[H_DIM];

// ---------------- packed f32x2 helpers ----------------
static __device__ __forceinline__ ull fma2(ull a, ull b, ull c) {
    ull d;
    asm("fma.rn.f32x2 %0, %1, %2, %3;" : "=l"(d) : "l"(a), "l"(b), "l"(c));
    return d;
}
static __device__ __forceinline__ ull add2(ull a, ull b) {
    ull d;
    asm("add.rn.f32x2 %0, %1, %2;" : "=l"(d) : "l"(a), "l"(b));
    return d;
}
static __device__ __forceinline__ float2 upk(ull a) {
    float2 r;
    asm("mov.b64 {%0, %1}, %2;" : "=f"(r.x), "=f"(r.y) : "l"(a));
    return r;
}
static __device__ __forceinline__ ull pk2(float x, float y) {
    ull r;
    asm("mov.b64 %0, {%1, %2};" : "=l"(r) : "f"(x), "f"(y));
    return r;
}

// ---------------- single-instruction MUFU.TANH ----------------
static __device__ __forceinline__ float tanhap(float x) {
    float r;
    asm("tanh.approx.f32 %0, %1;" : "=f"(r) : "f"(x));
    return r;
}

// Recurrence thread mapping for gate-row r (= g*64 + u):
// warp w = u>>4 owns units [16w,16w+16); even lane: gates (i,g); odd: (f,o)
static __device__ __forceinline__ int map_tid(int g, int u) {
    int odd = g & 1;                 // i,g -> even ; f,o -> odd
    return ((u >> 4) << 5) + ((u & 15) << 1) + odd;
}

// =====================================================================
// Kernel 1: xg = x @ W_ih.T + (b_ih + b_hh), permuted into slot streams.
// Sigmoid-gate entries (i, f, o) pre-scaled by 0.5 (exact in fp32).
// Grid: blockIdx.x = column group (4), blockIdx.y = t-tile (1024) so the
// 4 CTAs sharing one x-tile are launch-adjacent -> x read hits L2 3/4 times.
// =====================================================================
__global__ void gemm_xg(const float* __restrict__ x,
                        const float* __restrict__ Wih,
                        const float* __restrict__ bih,
                        const float* __restrict__ bhh) {
    __shared__ float xs[64][17];
    __shared__ float ws[64][17];
    const int tid = threadIdx.x;           // 0..255
    const int tx = tid & 15, ty = tid >> 4;
    const int row0 = blockIdx.y * 64;      // t-tile base
    const int col0 = blockIdx.x * 64;      // gate-row tile base

    float acc[4][4];
#pragma unroll
    for (int i = 0; i < 4; i++)
#pragma unroll
        for (int j = 0; j < 4; j++) acc[i][j] = 0.0f;

    const int l = tid * 4;
    const int lr = l >> 4, lk = l & 15;

    for (int kb = 0; kb < F_IN; kb += 16) {
        float4 xv = *(const float4*)(x + (size_t)(row0 + lr) * F_IN + kb + lk);
        float4 wv = *(const float4*)(Wih + (size_t)(col0 + lr) * F_IN + kb + lk);
        xs[lr][lk] = xv.x; xs[lr][lk + 1] = xv.y; xs[lr][lk + 2] = xv.z; xs[lr][lk + 3] = xv.w;
        ws[lr][lk] = wv.x; ws[lr][lk + 1] = wv.y; ws[lr][lk + 2] = wv.z; ws[lr][lk + 3] = wv.w;
        __syncthreads();
#pragma unroll
        for (int kk = 0; kk < 16; kk++) {
            float a[4], b[4];
#pragma unroll
            for (int i = 0; i < 4; i++) a[i] = xs[ty * 4 + i][kk];
#pragma unroll
            for (int j = 0; j < 4; j++) b[j] = ws[tx * 4 + j][kk];
#pragma unroll
            for (int i = 0; i < 4; i++)
#pragma unroll
                for (int j = 0; j < 4; j++) acc[i][j] = fmaf(a[i], b[j], acc[i][j]);
        }
        __syncthreads();
    }

    // Thread's 4 t-rows (t0 multiple of 4) form exactly one float4 block.
    const int tb4 = (row0 + ty * 4) >> 2;
#pragma unroll
    for (int j = 0; j < 4; j++) {
        const int col = col0 + tx * 4 + j;
        const float bj = bih[col] + bhh[col];
        const int gg = col >> 6;            // gate 0=i 1=f 2=g 3=o
        const int uu = col & 63;
        const int p = map_tid(gg, uu);
        const float sc = (gg == 2) ? 1.0f : 0.5f;   // sigmoid pre-scale (exact)
        float4 o;
        o.x = sc * (acc[0][j] + bj);
        o.y = sc * (acc[1][j] + bj);
        o.z = sc * (acc[2][j] + bj);
        o.w = sc * (acc[3][j] + bj);
        float4* buf = (gg >= 2) ? g_xgB : g_xgA;    // slot B = gates g,o
        buf[(size_t)tb4 * 128 + p] = o;
    }
}

// =====================================================================
// Kernel 2: persistent single-block LSTM recurrence, 128 threads
// (4 warps, 1 per SMSP). Even lane: gates (i, g) of unit u; odd: (f, o).
// One __syncthreads per step; gate product crosses via one shfl.
// (R7 structure verbatim — measured best at ~347 cyc/step.)
// =====================================================================
__global__ void __launch_bounds__(128, 1)
lstm_rec(const float* __restrict__ Whh,
         const float* __restrict__ h0,
         const float* __restrict__ c0) {
    __shared__ __align__(16) float h_sh[2][H_DIM];
    const int tid = threadIdx.x;          // 0..127
    const int l = tid & 31;
    const int u = ((tid >> 5) << 4) + (l >> 1);   // hidden unit
    const int odd = l & 1;
    const int rA = (odd ? 64 : 0) + u;    // i or f   (sigmoid: pre-scale 0.5)
    const int rB = (odd ? 192 : 128) + u; // g or o   (tanh 1.0 / sigmoid 0.5)
    const float scA = 0.5f;
    const float scB = odd ? 0.5f : 1.0f;

    // W_hh rows -> packed f32x2 registers, pre-scaled (x0.5 exact)
    ull wA[32], wB[32];
    {
        const float2* pa = (const float2*)(Whh + (size_t)rA * H_DIM);
        const float2* pb = (const float2*)(Whh + (size_t)rB * H_DIM);
#pragma unroll
        for (int i = 0; i < 32; i++) {
            float2 va = pa[i], vb = pb[i];
            wA[i] = pk2(scA * va.x, scA * va.y);
            wB[i] = pk2(scB * vb.x, scB * vb.y);
        }
    }

    const float aB = odd ? 0.5f : 1.0f;
    const float oB = odd ? 0.5f : 0.0f;

    float c = odd ? c0[u] : 0.0f;
    float h = 0.0f;
    if (tid < H_DIM) h_sh[0][tid] = h0[tid];

#define STEP(XA, XB, RB, WB) do {                                             \
        __syncthreads();                                                      \
        const ulonglong2* hp = (const ulonglong2*)h_sh[RB];                   \
        ull a0 = 0, a1 = 0, a2 = 0, a3 = 0;                                   \
        ull b0 = 0, b1 = 0, b2 = 0, b3 = 0;                                   \
        _Pragma("unroll")                                                     \
        for (int i = 0; i < 8; i++) {                                         \
            ulonglong2 hv = hp[2 * i], hw = hp[2 * i + 1];                    \
            a0 = fma2(hv.x, wA[4 * i + 0], a0);                               \
            b0 = fma2(hv.x, wB[4 * i + 0], b0);                               \
            a1 = fma2(hv.y, wA[4 * i + 1], a1);                               \
            b1 = fma2(hv.y, wB[4 * i + 1], b1);                               \
            a2 = fma2(hw.x, wA[4 * i + 2], a2);                               \
            b2 = fma2(hw.x, wB[4 * i + 2], b2);                               \
            a3 = fma2(hw.y, wA[4 * i + 3], a3);                               \
            b3 = fma2(hw.y, wB[4 * i + 3], b3);                               \
        }                                                                     \
        float2 sA = upk(add2(add2(a0, a1), add2(a2, a3)));                    \
        float2 sB = upk(add2(add2(b0, b1), add2(b2, b3)));                    \
        float preA = (XA) + sA.x + sA.y;                                      \
        float preB = (XB) + sB.x + sB.y;                                      \
        float vA = fmaf(0.5f, tanhap(preA), 0.5f);   /* sigmoid (pre-scaled)*/\
        float vB = fmaf(aB, tanhap(preB), oB);       /* tanh / sigmoid */     \
        float pr = __shfl_sync(0xffffffffu, vA * vB, l & 30);  /* i*g~ */     \
        if (odd) {                                                            \
            c = fmaf(vA, c, pr);            /* c = f*c + i*g~ */              \
            h = vB * tanhap(c);             /* h = o*tanh(c) */               \
            h_sh[WB][u] = h;                                                  \
        }                                                                     \
    } while (0)

    // Streamed xg: one LDG.128 pair per 4 steps, prefetched 2 blocks ahead
    // (padded arrays -> no bounds predicate).
    float4 xA0 = g_xgA[tid],       xB0 = g_xgB[tid];
    float4 xA1 = g_xgA[128 + tid], xB1 = g_xgB[128 + tid];
    for (int tb = 0; tb < NT4; tb++) {
        float4 xA2 = g_xgA[(size_t)(tb + 2) * 128 + tid];
        float4 xB2 = g_xgB[(size_t)(tb + 2) * 128 + tid];
        STEP(xA0.x, xB0.x, 0, 1);
        STEP(xA0.y, xB0.y, 1, 0);
        STEP(xA0.z, xB0.z, 0, 1);
        STEP(xA0.w, xB0.w, 1, 0);
        xA0 = xA1; xA1 = xA2;
        xB0 = xB1; xB1 = xB2;
    }
#undef STEP

    if (odd) g_hfin[u] = h;
}

// =====================================================================
// Kernel 3: out[f] = sigmoid(h_last . W_fc[f] + b_fc[f]),  f < 512
// =====================================================================
__global__ void fc_out(const float* __restrict__ Wfc,
                       const float* __restrict__ bfc,
                       float* __restrict__ out) {
    __shared__ float hsm[H_DIM];
    const int tid = threadIdx.x;   // 0..511
    if (tid < H_DIM) hsm[tid] = g_hfin[tid];
    __syncthreads();
    float acc = bfc[tid];
    const float* wr = Wfc + (size_t)tid * H_DIM;
#pragma unroll
    for (int k = 0; k < H_DIM; k++) acc = fmaf(wr[k], hsm[k], acc);
    out[tid] = 1.0f / (1.0f + __expf(-acc));
}

extern "C" void kernel_launch(void* const* d_in, const int* in_sizes, int n_in,
                              void* d_out, int out_size) {
    const float* x   = (const float*)d_in[0];
    const float* h0  = (const float*)d_in[1];
    const float* c0  = (const float*)d_in[2];
    const float* Wih = (const float*)d_in[3];
    const float* Whh = (const float*)d_in[4];
    const float* bih = (const float*)d_in[5];
    const float* bhh = (const float*)d_in[6];
    const float* Wfc = (const float*)d_in[7];
    const float* bfc = (const float*)d_in[8];
    float* out = (float*)d_out;

    dim3 ggrid(G_DIM / 64, T_SEQ / 64);   // x = colgroup (4), y = t-tile (1024)
    gemm_xg<<<ggrid, 256>>>(x, Wih, bih, bhh);
    lstm_rec<<<1, 128>>>(Whh, h0, c0);
    fc_out<<<1, 512>>>(Wfc, bfc, out);
}

// round 12
// speedup vs baseline: 1.6747x; 1.0021x over previous
#include <cuda_runtime.h>
#include <cuda_bf16.h>
#include <cstdint>

// Problem constants
#define T_SEQ 65536
#define F_IN  512
#define H_DIM 64
#define G_DIM 256    // 4*H
#define NT4   (T_SEQ / 4)

typedef unsigned long long ull;

// Scratch (allocation-free rule: __device__ globals)
// Slot streams as float4 (4 timesteps per load), padded +2 blocks so the
// prefetch needs no bounds predicate.
__device__ __align__(16) float4 g_xgA[(size_t)(NT4 + 2) * 128];
__device__ __align__(16) float4 g_xgB[(size_t)(NT4 + 2) * 128];
__device__ float g_hfin[H_DIM];

// ---------------- packed f32x2 helpers ----------------
static __device__ __forceinline__ ull fma2(ull a, ull b, ull c) {
    ull d;
    asm("fma.rn.f32x2 %0, %1, %2, %3;" : "=l"(d) : "l"(a), "l"(b), "l"(c));
    return d;
}
static __device__ __forceinline__ ull add2(ull a, ull b) {
    ull d;
    asm("add.rn.f32x2 %0, %1, %2;" : "=l"(d) : "l"(a), "l"(b));
    return d;
}
static __device__ __forceinline__ float2 upk(ull a) {
    float2 r;
    asm("mov.b64 {%0, %1}, %2;" : "=f"(r.x), "=f"(r.y) : "l"(a));
    return r;
}
static __device__ __forceinline__ ull pk2(float x, float y) {
    ull r;
    asm("mov.b64 %0, {%1, %2};" : "=l"(r) : "f"(x), "f"(y));
    return r;
}

// ---------------- single-instruction MUFU.TANH ----------------
static __device__ __forceinline__ float tanhap(float x) {
    float r;
    asm("tanh.approx.f32 %0, %1;" : "=f"(r) : "f"(x));
    return r;
}

// Recurrence thread mapping for gate-row r (= g*64 + u):
// warp w = u>>4 owns units [16w,16w+16); even lane: gates (i,g); odd: (f,o)
static __device__ __forceinline__ int map_tid(int g, int u) {
    int odd = g & 1;                 // i,g -> even ; f,o -> odd
    return ((u >> 4) << 5) + ((u & 15) << 1) + odd;
}

// =====================================================================
// Kernel 1: xg = x @ W_ih.T + (b_ih + b_hh), permuted into slot streams.
// f32x2-packed inner loop over k-major smem tiles:
//   per kk: 2x LDS.128 + 4 dup-MOV + 8 fma2  (vs 8 LDS + 16 FFMA before).
// Accumulation order per (row,col) is identical k-sequence -> xg is
// bit-identical to the scalar version.
// Grid: blockIdx.x = colgroup (4), blockIdx.y = t-tile (1024) for L2 x-reuse.
// =====================================================================
#define KSTRIDE 68   // 64 + 4 pad floats; multiple of 4 -> 16B-aligned rows
__global__ void gemm_xg(const float* __restrict__ x,
                        const float* __restrict__ Wih,
                        const float* __restrict__ bih,
                        const float* __restrict__ bhh) {
    __shared__ __align__(16) float xsT[16][KSTRIDE];   // [kk][row]
    __shared__ __align__(16) float wsT[16][KSTRIDE];   // [kk][col]
    const int tid = threadIdx.x;           // 0..255
    const int tx = tid & 15, ty = tid >> 4;
    const int row0 = blockIdx.y * 64;      // t-tile base
    const int col0 = blockIdx.x * 64;      // gate-row tile base

    // packed accumulators: acc2[i][jp] = {acc[i][2jp], acc[i][2jp+1]}
    ull acc2[4][2];
#pragma unroll
    for (int i = 0; i < 4; i++) { acc2[i][0] = 0ull; acc2[i][1] = 0ull; }

    const int l = tid * 4;
    const int lr = l >> 4, lk = l & 15;

    for (int kb = 0; kb < F_IN; kb += 16) {
        float4 xv = *(const float4*)(x + (size_t)(row0 + lr) * F_IN + kb + lk);
        float4 wv = *(const float4*)(Wih + (size_t)(col0 + lr) * F_IN + kb + lk);
        // transposed stores: [kk][row/col]
        xsT[lk + 0][lr] = xv.x; xsT[lk + 1][lr] = xv.y;
        xsT[lk + 2][lr] = xv.z; xsT[lk + 3][lr] = xv.w;
        wsT[lk + 0][lr] = wv.x; wsT[lk + 1][lr] = wv.y;
        wsT[lk + 2][lr] = wv.z; wsT[lk + 3][lr] = wv.w;
        __syncthreads();
#pragma unroll
        for (int kk = 0; kk < 16; kk++) {
            float4 av = *(const float4*)&xsT[kk][ty * 4];      // a[0..3]
            ulonglong2 bv = *(const ulonglong2*)&wsT[kk][tx * 4]; // {b0,b1},{b2,b3}
            ull aa0 = pk2(av.x, av.x);
            ull aa1 = pk2(av.y, av.y);
            ull aa2 = pk2(av.z, av.z);
            ull aa3 = pk2(av.w, av.w);
            acc2[0][0] = fma2(aa0, bv.x, acc2[0][0]);
            acc2[0][1] = fma2(aa0, bv.y, acc2[0][1]);
            acc2[1][0] = fma2(aa1, bv.x, acc2[1][0]);
            acc2[1][1] = fma2(aa1, bv.y, acc2[1][1]);
            acc2[2][0] = fma2(aa2, bv.x, acc2[2][0]);
            acc2[2][1] = fma2(aa2, bv.y, acc2[2][1]);
            acc2[3][0] = fma2(aa3, bv.x, acc2[3][0]);
            acc2[3][1] = fma2(aa3, bv.y, acc2[3][1]);
        }
        __syncthreads();
    }

    // Unpack to the scalar view used by the epilogue
    float acc[4][4];
#pragma unroll
    for (int i = 0; i < 4; i++) {
        float2 p0 = upk(acc2[i][0]);
        float2 p1 = upk(acc2[i][1]);
        acc[i][0] = p0.x; acc[i][1] = p0.y;
        acc[i][2] = p1.x; acc[i][3] = p1.y;
    }

    // Thread's 4 t-rows (t0 multiple of 4) form exactly one float4 block.
    const int tb4 = (row0 + ty * 4) >> 2;
#pragma unroll
    for (int j = 0; j < 4; j++) {
        const int col = col0 + tx * 4 + j;
        const float bj = bih[col] + bhh[col];
        const int gg = col >> 6;            // gate 0=i 1=f 2=g 3=o
        const int uu = col & 63;
        const int p = map_tid(gg, uu);
        const float sc = (gg == 2) ? 1.0f : 0.5f;   // sigmoid pre-scale (exact)
        float4 o;
        o.x = sc * (acc[0][j] + bj);
        o.y = sc * (acc[1][j] + bj);
        o.z = sc * (acc[2][j] + bj);
        o.w = sc * (acc[3][j] + bj);
        float4* buf = (gg >= 2) ? g_xgB : g_xgA;    // slot B = gates g,o
        buf[(size_t)tb4 * 128 + p] = o;
    }
}

// =====================================================================
// Kernel 2: persistent single-block LSTM recurrence, 128 threads
// (4 warps, 1 per SMSP). Even lane: gates (i, g) of unit u; odd: (f, o).
// One __syncthreads per step; gate product crosses via one shfl.
// (R7/R11 structure verbatim — measured best at ~347 cyc/step.)
// =====================================================================
__global__ void __launch_bounds__(128, 1)
lstm_rec(const float* __restrict__ Whh,
         const float* __restrict__ h0,
         const float* __restrict__ c0) {
    __shared__ __align__(16) float h_sh[2][H_DIM];
    const int tid = threadIdx.x;          // 0..127
    const int l = tid & 31;
    const int u = ((tid >> 5) << 4) + (l >> 1);   // hidden unit
    const int odd = l & 1;
    const int rA = (odd ? 64 : 0) + u;    // i or f   (sigmoid: pre-scale 0.5)
    const int rB = (odd ? 192 : 128) + u; // g or o   (tanh 1.0 / sigmoid 0.5)
    const float scA = 0.5f;
    const float scB = odd ? 0.5f : 1.0f;

    // W_hh rows -> packed f32x2 registers, pre-scaled (x0.5 exact)
    ull wA[32], wB[32];
    {
        const float2* pa = (const float2*)(Whh + (size_t)rA * H_DIM);
        const float2* pb = (const float2*)(Whh + (size_t)rB * H_DIM);
#pragma unroll
        for (int i = 0; i < 32; i++) {
            float2 va = pa[i], vb = pb[i];
            wA[i] = pk2(scA * va.x, scA * va.y);
            wB[i] = pk2(scB * vb.x, scB * vb.y);
        }
    }

    const float aB = odd ? 0.5f : 1.0f;
    const float oB = odd ? 0.5f : 0.0f;

    float c = odd ? c0[u] : 0.0f;
    float h = 0.0f;
    if (tid < H_DIM) h_sh[0][tid] = h0[tid];

#define STEP(XA, XB, RB, WB) do {                                             \
        __syncthreads();                                                      \
        const ulonglong2* hp = (const ulonglong2*)h_sh[RB];                   \
        ull a0 = 0, a1 = 0, a2 = 0, a3 = 0;                                   \
        ull b0 = 0, b1 = 0, b2 = 0, b3 = 0;                                   \
        _Pragma("unroll")                                                     \
        for (int i = 0; i < 8; i++) {                                         \
            ulonglong2 hv = hp[2 * i], hw = hp[2 * i + 1];                    \
            a0 = fma2(hv.x, wA[4 * i + 0], a0);                               \
            b0 = fma2(hv.x, wB[4 * i + 0], b0);                               \
            a1 = fma2(hv.y, wA[4 * i + 1], a1);                               \
            b1 = fma2(hv.y, wB[4 * i + 1], b1);                               \
            a2 = fma2(hw.x, wA[4 * i + 2], a2);                               \
            b2 = fma2(hw.x, wB[4 * i + 2], b2);                               \
            a3 = fma2(hw.y, wA[4 * i + 3], a3);                               \
            b3 = fma2(hw.y, wB[4 * i + 3], b3);                               \
        }                                                                     \
        float2 sA = upk(add2(add2(a0, a1), add2(a2, a3)));                    \
        float2 sB = upk(add2(add2(b0, b1), add2(b2, b3)));                    \
        float preA = (XA) + sA.x + sA.y;                                      \
        float preB = (XB) + sB.x + sB.y;                                      \
        float vA = fmaf(0.5f, tanhap(preA), 0.5f);   /* sigmoid (pre-scaled)*/\
        float vB = fmaf(aB, tanhap(preB), oB);       /* tanh / sigmoid */     \
        float pr = __shfl_sync(0xffffffffu, vA * vB, l & 30);  /* i*g~ */     \
        if (odd) {                                                            \
            c = fmaf(vA, c, pr);            /* c = f*c + i*g~ */              \
            h = vB * tanhap(c);             /* h = o*tanh(c) */               \
            h_sh[WB][u] = h;                                                  \
        }                                                                     \
    } while (0)

    // Streamed xg: one LDG.128 pair per 4 steps, prefetched 2 blocks ahead
    // (padded arrays -> no bounds predicate).
    float4 xA0 = g_xgA[tid],       xB0 = g_xgB[tid];
    float4 xA1 = g_xgA[128 + tid], xB1 = g_xgB[128 + tid];
    for (int tb = 0; tb < NT4; tb++) {
        float4 xA2 = g_xgA[(size_t)(tb + 2) * 128 + tid];
        float4 xB2 = g_xgB[(size_t)(tb + 2) * 128 + tid];
        STEP(xA0.x, xB0.x, 0, 1);
        STEP(xA0.y, xB0.y, 1, 0);
        STEP(xA0.z, xB0.z, 0, 1);
        STEP(xA0.w, xB0.w, 1, 0);
        xA0 = xA1; xA1 = xA2;
        xB0 = xB1; xB1 = xB2;
    }
#undef STEP

    if (odd) g_hfin[u] = h;
}

// =====================================================================
// Kernel 3: out[f] = sigmoid(h_last . W_fc[f] + b_fc[f]),  f < 512
// =====================================================================
__global__ void fc_out(const float* __restrict__ Wfc,
                       const float* __restrict__ bfc,
                       float* __restrict__ out) {
    __shared__ float hsm[H_DIM];
    const int tid = threadIdx.x;   // 0..511
    if (tid < H_DIM) hsm[tid] = g_hfin[tid];
    __syncthreads();
    float acc = bfc[tid];
    const float* wr = Wfc + (size_t)tid * H_DIM;
#pragma unroll
    for (int k = 0; k < H_DIM; k++) acc = fmaf(wr[k], hsm[k], acc);
    out[tid] = 1.0f / (1.0f + __expf(-acc));
}

extern "C" void kernel_launch(void* const* d_in, const int* in_sizes, int n_in,
                              void* d_out, int out_size) {
    const float* x   = (const float*)d_in[0];
    const float* h0  = (const float*)d_in[1];
    const float* c0  = (const float*)d_in[2];
    const float* Wih = (const float*)d_in[3];
    const float* Whh = (const float*)d_in[4];
    const float* bih = (const float*)d_in[5];
    const float* bhh = (const float*)d_in[6];
    const float* Wfc = (const float*)d_in[7];
    const float* bfc = (const float*)d_in[8];
    float* out = (float*)d_out;

    dim3 ggrid(G_DIM / 64, T_SEQ / 64);   // x = colgroup (4), y = t-tile (1024)
    gemm_xg<<<ggrid, 256>>>(x, Wih, bih, bhh);
    lstm_rec<<<1, 128>>>(Whh, h0, c0);
    fc_out<<<1, 512>>>(Wfc, bfc, out);
}

// round 13
// speedup vs baseline: 1.6884x; 1.0082x over previous
#include <cuda_runtime.h>
#include <cuda_bf16.h>
#include <cstdint>

// Problem constants
#define T_SEQ 65536
#define F_IN  512
#define H_DIM 64
#define G_DIM 256    // 4*H
#define NT4   (T_SEQ / 4)

typedef unsigned long long ull;

// Scratch (allocation-free rule: __device__ globals)
__device__ __align__(16) float4 g_xgA[(size_t)(NT4 + 2) * 128];
__device__ __align__(16) float4 g_xgB[(size_t)(NT4 + 2) * 128];
__device__ float g_hfin[H_DIM];

// ---------------- packed f32x2 helpers ----------------
static __device__ __forceinline__ ull fma2(ull a, ull b, ull c) {
    ull d;
    asm("fma.rn.f32x2 %0, %1, %2, %3;" : "=l"(d) : "l"(a), "l"(b), "l"(c));
    return d;
}
static __device__ __forceinline__ ull add2(ull a, ull b) {
    ull d;
    asm("add.rn.f32x2 %0, %1, %2;" : "=l"(d) : "l"(a), "l"(b));
    return d;
}
static __device__ __forceinline__ float2 upk(ull a) {
    float2 r;
    asm("mov.b64 {%0, %1}, %2;" : "=f"(r.x), "=f"(r.y) : "l"(a));
    return r;
}
static __device__ __forceinline__ ull pk2(float x, float y) {
    ull r;
    asm("mov.b64 %0, {%1, %2};" : "=l"(r) : "f"(x), "f"(y));
    return r;
}

// ---------------- single-instruction MUFU.TANH ----------------
static __device__ __forceinline__ float tanhap(float x) {
    float r;
    asm("tanh.approx.f32 %0, %1;" : "=f"(r) : "f"(x));
    return r;
}

// Recurrence thread mapping for gate-row r (= g*64 + u):
// warp w = u>>4 owns units [16w,16w+16); even lane: gates (i,g); odd: (f,o)
static __device__ __forceinline__ int map_tid(int g, int u) {
    int odd = g & 1;                 // i,g -> even ; f,o -> odd
    return ((u >> 4) << 5) + ((u & 15) << 1) + odd;
}

// =====================================================================
// Kernel 1: xg = x @ W_ih.T + (b_ih + b_hh), permuted into slot streams.
// BM=128, BN=64, f32x2 inner loop with accumulators packed over ROW
// PAIRS: per kk = 3x LDS.128 + 4 dup-MOV + 16 fma2 for 64 MACs.
// k-order per (row,col) identical -> xg bit-identical to prior rounds.
// Grid: blockIdx.x = colgroup (4), blockIdx.y = t-tile (512) for L2 x-reuse.
// =====================================================================
#define BM 128
#define XSTRIDE 132   // BM + 4 pad floats (16B-aligned rows)
#define WSTRIDE 68    // 64 + 4 pad floats
__global__ void gemm_xg(const float* __restrict__ x,
                        const float* __restrict__ Wih,
                        const float* __restrict__ bih,
                        const float* __restrict__ bhh) {
    __shared__ __align__(16) float xsT[16][XSTRIDE];   // [kk][row]
    __shared__ __align__(16) float wsT[16][WSTRIDE];   // [kk][col]
    const int tid = threadIdx.x;           // 0..255
    const int tx = tid & 15;               // col group: 4 cols
    const int ty = tid >> 4;               // row group: 8 rows
    const int row0 = blockIdx.y * BM;      // t-tile base
    const int col0 = blockIdx.x * 64;      // gate-row tile base

    // acc2[rp][j] = {acc[2rp][j], acc[2rp+1][j]}  (rows packed in pairs)
    ull acc2[4][4];
#pragma unroll
    for (int i = 0; i < 4; i++)
#pragma unroll
        for (int j = 0; j < 4; j++) acc2[i][j] = 0ull;

    // Loader indices: x tile 128x16 = 512 float4 slots (2 per thread),
    // W tile 64x16 = 256 float4 slots (1 per thread).
    const int xr0 = tid >> 2, xk = (tid & 3) * 4;          // slot tid
    const int xr1 = (tid + 256) >> 2;                      // slot tid+256
    const int wr_ = tid >> 2, wk = (tid & 3) * 4;

    for (int kb = 0; kb < F_IN; kb += 16) {
        float4 xv0 = *(const float4*)(x + (size_t)(row0 + xr0) * F_IN + kb + xk);
        float4 xv1 = *(const float4*)(x + (size_t)(row0 + xr1) * F_IN + kb + xk);
        float4 wv = *(const float4*)(Wih + (size_t)(col0 + wr_) * F_IN + kb + wk);
        xsT[xk + 0][xr0] = xv0.x; xsT[xk + 1][xr0] = xv0.y;
        xsT[xk + 2][xr0] = xv0.z; xsT[xk + 3][xr0] = xv0.w;
        xsT[xk + 0][xr1] = xv1.x; xsT[xk + 1][xr1] = xv1.y;
        xsT[xk + 2][xr1] = xv1.z; xsT[xk + 3][xr1] = xv1.w;
        wsT[wk + 0][wr_] = wv.x; wsT[wk + 1][wr_] = wv.y;
        wsT[wk + 2][wr_] = wv.z; wsT[wk + 3][wr_] = wv.w;
        __syncthreads();
#pragma unroll
        for (int kk = 0; kk < 16; kk++) {
            // rows ty*8..ty*8+7 as 4 packed pairs (2x LDS.128, warp-broadcast)
            ulonglong2 a01 = *(const ulonglong2*)&xsT[kk][ty * 8];
            ulonglong2 a23 = *(const ulonglong2*)&xsT[kk][ty * 8 + 4];
            // cols tx*4..tx*4+3 (1x LDS.128), duplicated into pairs
            float4 bv = *(const float4*)&wsT[kk][tx * 4];
            ull bb0 = pk2(bv.x, bv.x);
            ull bb1 = pk2(bv.y, bv.y);
            ull bb2 = pk2(bv.z, bv.z);
            ull bb3 = pk2(bv.w, bv.w);
            acc2[0][0] = fma2(a01.x, bb0, acc2[0][0]);
            acc2[0][1] = fma2(a01.x, bb1, acc2[0][1]);
            acc2[0][2] = fma2(a01.x, bb2, acc2[0][2]);
            acc2[0][3] = fma2(a01.x, bb3, acc2[0][3]);
            acc2[1][0] = fma2(a01.y, bb0, acc2[1][0]);
            acc2[1][1] = fma2(a01.y, bb1, acc2[1][1]);
            acc2[1][2] = fma2(a01.y, bb2, acc2[1][2]);
            acc2[1][3] = fma2(a01.y, bb3, acc2[1][3]);
            acc2[2][0] = fma2(a23.x, bb0, acc2[2][0]);
            acc2[2][1] = fma2(a23.x, bb1, acc2[2][1]);
            acc2[2][2] = fma2(a23.x, bb2, acc2[2][2]);
            acc2[2][3] = fma2(a23.x, bb3, acc2[2][3]);
            acc2[3][0] = fma2(a23.y, bb0, acc2[3][0]);
            acc2[3][1] = fma2(a23.y, bb1, acc2[3][1]);
            acc2[3][2] = fma2(a23.y, bb2, acc2[3][2]);
            acc2[3][3] = fma2(a23.y, bb3, acc2[3][3]);
        }
        __syncthreads();
    }

    // Epilogue: thread's 8 rows = 2 float4 t-blocks; 4 cols.
    const int tb4 = (row0 + ty * 8) >> 2;
#pragma unroll
    for (int j = 0; j < 4; j++) {
        const int col = col0 + tx * 4 + j;
        const float bj = bih[col] + bhh[col];
        const int gg = col >> 6;            // gate 0=i 1=f 2=g 3=o
        const int uu = col & 63;
        const int p = map_tid(gg, uu);
        const float sc = (gg == 2) ? 1.0f : 0.5f;   // sigmoid pre-scale (exact)
        float v[8];
#pragma unroll
        for (int rp = 0; rp < 4; rp++) {
            float2 pv = upk(acc2[rp][j]);
            v[2 * rp] = pv.x;
            v[2 * rp + 1] = pv.y;
        }
        float4* buf = (gg >= 2) ? g_xgB : g_xgA;    // slot B = gates g,o
#pragma unroll
        for (int m = 0; m < 2; m++) {
            float4 o;
            o.x = sc * (v[4 * m + 0] + bj);
            o.y = sc * (v[4 * m + 1] + bj);
            o.z = sc * (v[4 * m + 2] + bj);
            o.w = sc * (v[4 * m + 3] + bj);
            buf[(size_t)(tb4 + m) * 128 + p] = o;
        }
    }
}

// =====================================================================
// Kernel 2: persistent single-block LSTM recurrence, 128 threads
// (4 warps, 1 per SMSP). Even lane: gates (i, g) of unit u; odd: (f, o).
// One __syncthreads per step; gate product crosses via one shfl.
// (Measured best structure, ~347 cyc/step — verbatim.)
// =====================================================================
__global__ void __launch_bounds__(128, 1)
lstm_rec(const float* __restrict__ Whh,
         const float* __restrict__ h0,
         const float* __restrict__ c0) {
    __shared__ __align__(16) float h_sh[2][H_DIM];
    const int tid = threadIdx.x;          // 0..127
    const int l = tid & 31;
    const int u = ((tid >> 5) << 4) + (l >> 1);   // hidden unit
    const int odd = l & 1;
    const int rA = (odd ? 64 : 0) + u;    // i or f   (sigmoid: pre-scale 0.5)
    const int rB = (odd ? 192 : 128) + u; // g or o   (tanh 1.0 / sigmoid 0.5)
    const float scA = 0.5f;
    const float scB = odd ? 0.5f : 1.0f;

    // W_hh rows -> packed f32x2 registers, pre-scaled (x0.5 exact)
    ull wA[32], wB[32];
    {
        const float2* pa = (const float2*)(Whh + (size_t)rA * H_DIM);
        const float2* pb = (const float2*)(Whh + (size_t)rB * H_DIM);
#pragma unroll
        for (int i = 0; i < 32; i++) {
            float2 va = pa[i], vb = pb[i];
            wA[i] = pk2(scA * va.x, scA * va.y);
            wB[i] = pk2(scB * vb.x, scB * vb.y);
        }
    }

    const float aB = odd ? 0.5f : 1.0f;
    const float oB = odd ? 0.5f : 0.0f;

    float c = odd ? c0[u] : 0.0f;
    float h = 0.0f;
    if (tid < H_DIM) h_sh[0][tid] = h0[tid];

#define STEP(XA, XB, RB, WB) do {                                             \
        __syncthreads();                                                      \
        const ulonglong2* hp = (const ulonglong2*)h_sh[RB];                   \
        ull a0 = 0, a1 = 0, a2 = 0, a3 = 0;                                   \
        ull b0 = 0, b1 = 0, b2 = 0, b3 = 0;                                   \
        _Pragma("unroll")                                                     \
        for (int i = 0; i < 8; i++) {                                         \
            ulonglong2 hv = hp[2 * i], hw = hp[2 * i + 1];                    \
            a0 = fma2(hv.x, wA[4 * i + 0], a0);                               \
            b0 = fma2(hv.x, wB[4 * i + 0], b0);                               \
            a1 = fma2(hv.y, wA[4 * i + 1], a1);                               \
            b1 = fma2(hv.y, wB[4 * i + 1], b1);                               \
            a2 = fma2(hw.x, wA[4 * i + 2], a2);                               \
            b2 = fma2(hw.x, wB[4 * i + 2], b2);                               \
            a3 = fma2(hw.y, wA[4 * i + 3], a3);                               \
            b3 = fma2(hw.y, wB[4 * i + 3], b3);                               \
        }                                                                     \
        float2 sA = upk(add2(add2(a0, a1), add2(a2, a3)));                    \
        float2 sB = upk(add2(add2(b0, b1), add2(b2, b3)));                    \
        float preA = (XA) + sA.x + sA.y;                                      \
        float preB = (XB) + sB.x + sB.y;                                      \
        float vA = fmaf(0.5f, tanhap(preA), 0.5f);   /* sigmoid (pre-scaled)*/\
        float vB = fmaf(aB, tanhap(preB), oB);       /* tanh / sigmoid */     \
        float pr = __shfl_sync(0xffffffffu, vA * vB, l & 30);  /* i*g~ */     \
        if (odd) {                                                            \
            c = fmaf(vA, c, pr);            /* c = f*c + i*g~ */              \
            h = vB * tanhap(c);             /* h = o*tanh(c) */               \
            h_sh[WB][u] = h;                                                  \
        }                                                                     \
    } while (0)

    // Streamed xg: one LDG.128 pair per 4 steps, prefetched 2 blocks ahead
    // (padded arrays -> no bounds predicate).
    float4 xA0 = g_xgA[tid],       xB0 = g_xgB[tid];
    float4 xA1 = g_xgA[128 + tid], xB1 = g_xgB[128 + tid];
    for (int tb = 0; tb < NT4; tb++) {
        float4 xA2 = g_xgA[(size_t)(tb + 2) * 128 + tid];
        float4 xB2 = g_xgB[(size_t)(tb + 2) * 128 + tid];
        STEP(xA0.x, xB0.x, 0, 1);
        STEP(xA0.y, xB0.y, 1, 0);
        STEP(xA0.z, xB0.z, 0, 1);
        STEP(xA0.w, xB0.w, 1, 0);
        xA0 = xA1; xA1 = xA2;
        xB0 = xB1; xB1 = xB2;
    }
#undef STEP

    if (odd) g_hfin[u] = h;
}

// =====================================================================
// Kernel 3: out[f] = sigmoid(h_last . W_fc[f] + b_fc[f]),  f < 512
// =====================================================================
__global__ void fc_out(const float* __restrict__ Wfc,
                       const float* __restrict__ bfc,
                       float* __restrict__ out) {
    __shared__ float hsm[H_DIM];
    const int tid = threadIdx.x;   // 0..511
    if (tid < H_DIM) hsm[tid] = g_hfin[tid];
    __syncthreads();
    float acc = bfc[tid];
    const float* wr = Wfc + (size_t)tid * H_DIM;
#pragma unroll
    for (int k = 0; k < H_DIM; k++) acc = fmaf(wr[k], hsm[k], acc);
    out[tid] = 1.0f / (1.0f + __expf(-acc));
}

extern "C" void kernel_launch(void* const* d_in, const int* in_sizes, int n_in,
                              void* d_out, int out_size) {
    const float* x   = (const float*)d_in[0];
    const float* h0  = (const float*)d_in[1];
    const float* c0  = (const float*)d_in[2];
    const float* Wih = (const float*)d_in[3];
    const float* Whh = (const float*)d_in[4];
    const float* bih = (const float*)d_in[5];
    const float* bhh = (const float*)d_in[6];
    const float* Wfc = (const float*)d_in[7];
    const float* bfc = (const float*)d_in[8];
    float* out = (float*)d_out;

    dim3 ggrid(G_DIM / 64, T_SEQ / BM);   // x = colgroup (4), y = t-tile (512)
    gemm_xg<<<ggrid, 256>>>(x, Wih, bih, bhh);
    lstm_rec<<<1, 128>>>(Whh, h0, c0);
    fc_out<<<1, 512>>>(Wfc, bfc, out);
}

// round 14
// speedup vs baseline: 1.7004x; 1.0071x over previous
#include <cuda_runtime.h>
#include <cuda_bf16.h>
#include <cstdint>

// Problem constants
#define T_SEQ 65536
#define F_IN  512
#define H_DIM 64
#define G_DIM 256    // 4*H
#define NT4   (T_SEQ / 4)

typedef unsigned long long ull;

// Scratch (allocation-free rule: __device__ globals)
__device__ __align__(16) float4 g_xgA[(size_t)(NT4 + 2) * 128];
__device__ __align__(16) float4 g_xgB[(size_t)(NT4 + 2) * 128];
__device__ float g_hfin[H_DIM];

// ---------------- packed f32x2 helpers ----------------
static __device__ __forceinline__ ull fma2(ull a, ull b, ull c) {
    ull d;
    asm("fma.rn.f32x2 %0, %1, %2, %3;" : "=l"(d) : "l"(a), "l"(b), "l"(c));
    return d;
}
static __device__ __forceinline__ ull add2(ull a, ull b) {
    ull d;
    asm("add.rn.f32x2 %0, %1, %2;" : "=l"(d) : "l"(a), "l"(b));
    return d;
}
static __device__ __forceinline__ float2 upk(ull a) {
    float2 r;
    asm("mov.b64 {%0, %1}, %2;" : "=f"(r.x), "=f"(r.y) : "l"(a));
    return r;
}
static __device__ __forceinline__ ull pk2(float x, float y) {
    ull r;
    asm("mov.b64 %0, {%1, %2};" : "=l"(r) : "f"(x), "f"(y));
    return r;
}

// ---------------- single-instruction MUFU.TANH ----------------
static __device__ __forceinline__ float tanhap(float x) {
    float r;
    asm("tanh.approx.f32 %0, %1;" : "=f"(r) : "f"(x));
    return r;
}

// Recurrence thread mapping for gate-row r (= g*64 + u):
// warp w = u>>4 owns units [16w,16w+16); even lane: gates (i,g); odd: (f,o)
static __device__ __forceinline__ int map_tid(int g, int u) {
    int odd = g & 1;                 // i,g -> even ; f,o -> odd
    return ((u >> 4) << 5) + ((u & 15) << 1) + odd;
}

// =====================================================================
// Kernel 1: xg = x @ W_ih.T + (b_ih + b_hh), permuted into slot streams.
// BM=128, BN=128, double-buffered smem, f32x2 inner loop with row-pair
// packed accumulators. Thread tile 8 rows x 8 cols; the 8 cols are split
// tx*4 and 64+tx*4 so both b-side LDS.128 stay at 2-way conflicts.
// Per kk: 4x LDS.128 + 8 dup-MOV + 32 fma2 for 64 MACs.
// k-order per (row,col) identical -> xg bit-identical to prior rounds.
// Grid: blockIdx.x = colgroup (2), blockIdx.y = t-tile (512) for L2 x-reuse.
// =====================================================================
#define BM 128
#define BN 128
#define XSTRIDE 132   // 128 + 4 pad floats (16B-aligned rows)
#define NKT (F_IN / 16)
__global__ void __launch_bounds__(256)
gemm_xg(const float* __restrict__ x,
        const float* __restrict__ Wih,
        const float* __restrict__ bih,
        const float* __restrict__ bhh) {
    __shared__ __align__(16) float xsT[2][16][XSTRIDE];   // [buf][kk][row]
    __shared__ __align__(16) float wsT[2][16][XSTRIDE];   // [buf][kk][col]
    const int tid = threadIdx.x;           // 0..255
    const int tx = tid & 15;               // col group
    const int ty = tid >> 4;               // row group: rows ty*8..ty*8+7
    const int row0 = blockIdx.y * BM;      // t-tile base
    const int col0 = blockIdx.x * BN;      // gate-row tile base

    // acc2[rp][jj]: rp = row pair (rows 2rp,2rp+1), jj = col slot
    // col(jj) = (jj<4) ? tx*4+jj : 64 + tx*4 + (jj-4)
    ull acc2[4][8];
#pragma unroll
    for (int i = 0; i < 4; i++)
#pragma unroll
        for (int j = 0; j < 8; j++) acc2[i][j] = 0ull;

    // Loader: both tiles are 128x16 = 512 float4 slots, 2 per thread.
    const int r0 = tid >> 2, r1 = (tid + 256) >> 2;
    const int kq = (tid & 3) * 4;

#define STS_TILE(BUF, XV0, XV1, WV0, WV1) do {                                \
        xsT[BUF][kq + 0][r0] = (XV0).x; xsT[BUF][kq + 1][r0] = (XV0).y;       \
        xsT[BUF][kq + 2][r0] = (XV0).z; xsT[BUF][kq + 3][r0] = (XV0).w;       \
        xsT[BUF][kq + 0][r1] = (XV1).x; xsT[BUF][kq + 1][r1] = (XV1).y;       \
        xsT[BUF][kq + 2][r1] = (XV1).z; xsT[BUF][kq + 3][r1] = (XV1).w;       \
        wsT[BUF][kq + 0][r0] = (WV0).x; wsT[BUF][kq + 1][r0] = (WV0).y;       \
        wsT[BUF][kq + 2][r0] = (WV0).z; wsT[BUF][kq + 3][r0] = (WV0).w;       \
        wsT[BUF][kq + 0][r1] = (WV1).x; wsT[BUF][kq + 1][r1] = (WV1).y;       \
        wsT[BUF][kq + 2][r1] = (WV1).z; wsT[BUF][kq + 3][r1] = (WV1).w;       \
    } while (0)

    // Prologue: load ktile 0 into buffer 0.
    {
        float4 xv0 = *(const float4*)(x + (size_t)(row0 + r0) * F_IN + kq);
        float4 xv1 = *(const float4*)(x + (size_t)(row0 + r1) * F_IN + kq);
        float4 wv0 = *(const float4*)(Wih + (size_t)(col0 + r0) * F_IN + kq);
        float4 wv1 = *(const float4*)(Wih + (size_t)(col0 + r1) * F_IN + kq);
        STS_TILE(0, xv0, xv1, wv0, wv1);
    }
    __syncthreads();

    for (int kt = 0; kt < NKT; kt++) {
        const int cur = kt & 1;
        float4 nx0, nx1, nw0, nw1;
        if (kt + 1 < NKT) {
            const int kb = (kt + 1) * 16 + kq;
            nx0 = *(const float4*)(x + (size_t)(row0 + r0) * F_IN + kb);
            nx1 = *(const float4*)(x + (size_t)(row0 + r1) * F_IN + kb);
            nw0 = *(const float4*)(Wih + (size_t)(col0 + r0) * F_IN + kb);
            nw1 = *(const float4*)(Wih + (size_t)(col0 + r1) * F_IN + kb);
        }
#pragma unroll
        for (int kk = 0; kk < 16; kk++) {
            ulonglong2 a01 = *(const ulonglong2*)&xsT[cur][kk][ty * 8];
            ulonglong2 a23 = *(const ulonglong2*)&xsT[cur][kk][ty * 8 + 4];
            float4 bv0 = *(const float4*)&wsT[cur][kk][tx * 4];
            float4 bv1 = *(const float4*)&wsT[cur][kk][64 + tx * 4];
            ull b0 = pk2(bv0.x, bv0.x), b1 = pk2(bv0.y, bv0.y);
            ull b2 = pk2(bv0.z, bv0.z), b3 = pk2(bv0.w, bv0.w);
            ull b4 = pk2(bv1.x, bv1.x), b5 = pk2(bv1.y, bv1.y);
            ull b6 = pk2(bv1.z, bv1.z), b7 = pk2(bv1.w, bv1.w);
            acc2[0][0] = fma2(a01.x, b0, acc2[0][0]);
            acc2[0][1] = fma2(a01.x, b1, acc2[0][1]);
            acc2[0][2] = fma2(a01.x, b2, acc2[0][2]);
            acc2[0][3] = fma2(a01.x, b3, acc2[0][3]);
            acc2[0][4] = fma2(a01.x, b4, acc2[0][4]);
            acc2[0][5] = fma2(a01.x, b5, acc2[0][5]);
            acc2[0][6] = fma2(a01.x, b6, acc2[0][6]);
            acc2[0][7] = fma2(a01.x, b7, acc2[0][7]);
            acc2[1][0] = fma2(a01.y, b0, acc2[1][0]);
            acc2[1][1] = fma2(a01.y, b1, acc2[1][1]);
            acc2[1][2] = fma2(a01.y, b2, acc2[1][2]);
            acc2[1][3] = fma2(a01.y, b3, acc2[1][3]);
            acc2[1][4] = fma2(a01.y, b4, acc2[1][4]);
            acc2[1][5] = fma2(a01.y, b5, acc2[1][5]);
            acc2[1][6] = fma2(a01.y, b6, acc2[1][6]);
            acc2[1][7] = fma2(a01.y, b7, acc2[1][7]);
            acc2[2][0] = fma2(a23.x, b0, acc2[2][0]);
            acc2[2][1] = fma2(a23.x, b1, acc2[2][1]);
            acc2[2][2] = fma2(a23.x, b2, acc2[2][2]);
            acc2[2][3] = fma2(a23.x, b3, acc2[2][3]);
            acc2[2][4] = fma2(a23.x, b4, acc2[2][4]);
            acc2[2][5] = fma2(a23.x, b5, acc2[2][5]);
            acc2[2][6] = fma2(a23.x, b6, acc2[2][6]);
            acc2[2][7] = fma2(a23.x, b7, acc2[2][7]);
            acc2[3][0] = fma2(a23.y, b0, acc2[3][0]);
            acc2[3][1] = fma2(a23.y, b1, acc2[3][1]);
            acc2[3][2] = fma2(a23.y, b2, acc2[3][2]);
            acc2[3][3] = fma2(a23.y, b3, acc2[3][3]);
            acc2[3][4] = fma2(a23.y, b4, acc2[3][4]);
            acc2[3][5] = fma2(a23.y, b5, acc2[3][5]);
            acc2[3][6] = fma2(a23.y, b6, acc2[3][6]);
            acc2[3][7] = fma2(a23.y, b7, acc2[3][7]);
        }
        if (kt + 1 < NKT) STS_TILE(cur ^ 1, nx0, nx1, nw0, nw1);
        __syncthreads();
    }
#undef STS_TILE

    // Epilogue: thread's 8 rows = 2 float4 t-blocks; 8 cols (two groups).
    const int tb4 = (row0 + ty * 8) >> 2;
#pragma unroll
    for (int jj = 0; jj < 8; jj++) {
        const int col = col0 + ((jj < 4) ? (tx * 4 + jj) : (64 + tx * 4 + jj - 4));
        const float bj = bih[col] + bhh[col];
        const int gg = col >> 6;            // gate 0=i 1=f 2=g 3=o
        const int uu = col & 63;
        const int p = map_tid(gg, uu);
        const float sc = (gg == 2) ? 1.0f : 0.5f;   // sigmoid pre-scale (exact)
        float v[8];
#pragma unroll
        for (int rp = 0; rp < 4; rp++) {
            float2 pv = upk(acc2[rp][jj]);
            v[2 * rp] = pv.x;
            v[2 * rp + 1] = pv.y;
        }
        float4* buf = (gg >= 2) ? g_xgB : g_xgA;    // slot B = gates g,o
#pragma unroll
        for (int m = 0; m < 2; m++) {
            float4 o;
            o.x = sc * (v[4 * m + 0] + bj);
            o.y = sc * (v[4 * m + 1] + bj);
            o.z = sc * (v[4 * m + 2] + bj);
            o.w = sc * (v[4 * m + 3] + bj);
            buf[(size_t)(tb4 + m) * 128 + p] = o;
        }
    }
}

// =====================================================================
// Kernel 2: persistent single-block LSTM recurrence, 128 threads
// (4 warps, 1 per SMSP). Even lane: gates (i, g) of unit u; odd: (f, o).
// One __syncthreads per step; gate product crosses via one shfl.
// (Measured best structure, ~347 cyc/step — verbatim.)
// =====================================================================
__global__ void __launch_bounds__(128, 1)
lstm_rec(const float* __restrict__ Whh,
         const float* __restrict__ h0,
         const float* __restrict__ c0) {
    __shared__ __align__(16) float h_sh[2][H_DIM];
    const int tid = threadIdx.x;          // 0..127
    const int l = tid & 31;
    const int u = ((tid >> 5) << 4) + (l >> 1);   // hidden unit
    const int odd = l & 1;
    const int rA = (odd ? 64 : 0) + u;    // i or f   (sigmoid: pre-scale 0.5)
    const int rB = (odd ? 192 : 128) + u; // g or o   (tanh 1.0 / sigmoid 0.5)
    const float scA = 0.5f;
    const float scB = odd ? 0.5f : 1.0f;

    // W_hh rows -> packed f32x2 registers, pre-scaled (x0.5 exact)
    ull wA[32], wB[32];
    {
        const float2* pa = (const float2*)(Whh + (size_t)rA * H_DIM);
        const float2* pb = (const float2*)(Whh + (size_t)rB * H_DIM);
#pragma unroll
        for (int i = 0; i < 32; i++) {
            float2 va = pa[i], vb = pb[i];
            wA[i] = pk2(scA * va.x, scA * va.y);
            wB[i] = pk2(scB * vb.x, scB * vb.y);
        }
    }

    const float aB = odd ? 0.5f : 1.0f;
    const float oB = odd ? 0.5f : 0.0f;

    float c = odd ? c0[u] : 0.0f;
    float h = 0.0f;
    if (tid < H_DIM) h_sh[0][tid] = h0[tid];

#define STEP(XA, XB, RB, WB) do {                                             \
        __syncthreads();                                                      \
        const ulonglong2* hp = (const ulonglong2*)h_sh[RB];                   \
        ull a0 = 0, a1 = 0, a2 = 0, a3 = 0;                                   \
        ull b0 = 0, b1 = 0, b2 = 0, b3 = 0;                                   \
        _Pragma("unroll")                                                     \
        for (int i = 0; i < 8; i++) {                                         \
            ulonglong2 hv = hp[2 * i], hw = hp[2 * i + 1];                    \
            a0 = fma2(hv.x, wA[4 * i + 0], a0);                               \
            b0 = fma2(hv.x, wB[4 * i + 0], b0);                               \
            a1 = fma2(hv.y, wA[4 * i + 1], a1);                               \
            b1 = fma2(hv.y, wB[4 * i + 1], b1);                               \
            a2 = fma2(hw.x, wA[4 * i + 2], a2);                               \
            b2 = fma2(hw.x, wB[4 * i + 2], b2);                               \
            a3 = fma2(hw.y, wA[4 * i + 3], a3);                               \
            b3 = fma2(hw.y, wB[4 * i + 3], b3);                               \
        }                                                                     \
        float2 sA = upk(add2(add2(a0, a1), add2(a2, a3)));                    \
        float2 sB = upk(add2(add2(b0, b1), add2(b2, b3)));                    \
        float preA = (XA) + sA.x + sA.y;                                      \
        float preB = (XB) + sB.x + sB.y;                                      \
        float vA = fmaf(0.5f, tanhap(preA), 0.5f);   /* sigmoid (pre-scaled)*/\
        float vB = fmaf(aB, tanhap(preB), oB);       /* tanh / sigmoid */     \
        float pr = __shfl_sync(0xffffffffu, vA * vB, l & 30);  /* i*g~ */     \
        if (odd) {                                                            \
            c = fmaf(vA, c, pr);            /* c = f*c + i*g~ */              \
            h = vB * tanhap(c);             /* h = o*tanh(c) */               \
            h_sh[WB][u] = h;                                                  \
        }                                                                     \
    } while (0)

    // Streamed xg: one LDG.128 pair per 4 steps, prefetched 2 blocks ahead
    // (padded arrays -> no bounds predicate).
    float4 xA0 = g_xgA[tid],       xB0 = g_xgB[tid];
    float4 xA1 = g_xgA[128 + tid], xB1 = g_xgB[128 + tid];
    for (int tb = 0; tb < NT4; tb++) {
        float4 xA2 = g_xgA[(size_t)(tb + 2) * 128 + tid];
        float4 xB2 = g_xgB[(size_t)(tb + 2) * 128 + tid];
        STEP(xA0.x, xB0.x, 0, 1);
        STEP(xA0.y, xB0.y, 1, 0);
        STEP(xA0.z, xB0.z, 0, 1);
        STEP(xA0.w, xB0.w, 1, 0);
        xA0 = xA1; xA1 = xA2;
        xB0 = xB1; xB1 = xB2;
    }
#undef STEP

    if (odd) g_hfin[u] = h;
}

// =====================================================================
// Kernel 3: out[f] = sigmoid(h_last . W_fc[f] + b_fc[f]),  f < 512
// =====================================================================
__global__ void fc_out(const float* __restrict__ Wfc,
                       const float* __restrict__ bfc,
                       float* __restrict__ out) {
    __shared__ float hsm[H_DIM];
    const int tid = threadIdx.x;   // 0..511
    if (tid < H_DIM) hsm[tid] = g_hfin[tid];
    __syncthreads();
    float acc = bfc[tid];
    const float* wr = Wfc + (size_t)tid * H_DIM;
#pragma unroll
    for (int k = 0; k < H_DIM; k++) acc = fmaf(wr[k], hsm[k], acc);
    out[tid] = 1.0f / (1.0f + __expf(-acc));
}

extern "C" void kernel_launch(void* const* d_in, const int* in_sizes, int n_in,
                              void* d_out, int out_size) {
    const float* x   = (const float*)d_in[0];
    const float* h0  = (const float*)d_in[1];
    const float* c0  = (const float*)d_in[2];
    const float* Wih = (const float*)d_in[3];
    const float* Whh = (const float*)d_in[4];
    const float* bih = (const float*)d_in[5];
    const float* bhh = (const float*)d_in[6];
    const float* Wfc = (const float*)d_in[7];
    const float* bfc = (const float*)d_in[8];
    float* out = (float*)d_out;

    dim3 ggrid(G_DIM / BN, T_SEQ / BM);   // x = colgroup (2), y = t-tile (512)
    gemm_xg<<<ggrid, 256>>>(x, Wih, bih, bhh);
    lstm_rec<<<1, 128>>>(Whh, h0, c0);
    fc_out<<<1, 512>>>(Wfc, bfc, out);
}